// round 14
// baseline (speedup 1.0000x reference)
#include <cuda_runtime.h>
#include <cuda_fp16.h>
#include <cstdint>

#define Bb 8
#define Nn 1024
#define Cc 1024
#define Hh 16
#define Dd 64
#define NDh (Nn * Dd)

// ---------------- scratch (device globals; allocation-free) ----------------
__device__ __align__(16) __half g_x[Bb * Nn * Cc];                // x, fp16
__device__ __align__(16) __half g_wih[3 * Cc * Cc], g_wil[3 * Cc * Cc];
__device__ __align__(16) __half g_woh[Cc * Cc], g_wol[Cc * Cc];
__device__ __align__(16) __half g_q[Bb * Hh * NDh];               // q single (scaled)
__device__ __align__(16) __half g_kh[Bb * Hh * NDh], g_kl[Bb * Hh * NDh];
__device__ __align__(16) __half g_vh[Bb * Hh * NDh], g_vl[Bb * Hh * NDh];
__device__ __align__(16) __half g_ao[Bb * Nn * Cc];               // attn out single

// ---------------------------- PTX helpers ----------------------------------
#define LDSM4(r0, r1, r2, r3, addr)                                          \
    asm volatile("ldmatrix.sync.aligned.m8n8.x4.shared.b16 {%0,%1,%2,%3},[%4];" \
                 : "=r"(r0), "=r"(r1), "=r"(r2), "=r"(r3) : "r"(addr))
#define LDSM4T(r0, r1, r2, r3, addr)                                         \
    asm volatile("ldmatrix.sync.aligned.m8n8.x4.trans.shared.b16 {%0,%1,%2,%3},[%4];" \
                 : "=r"(r0), "=r"(r1), "=r"(r2), "=r"(r3) : "r"(addr))
#define MMA16816(c, a, b)                                                    \
    asm volatile("mma.sync.aligned.m16n8k16.row.col.f32.f16.f16.f32 "        \
                 "{%0,%1,%2,%3},{%4,%5,%6,%7},{%8,%9},{%0,%1,%2,%3};"        \
                 : "+f"((c)[0]), "+f"((c)[1]), "+f"((c)[2]), "+f"((c)[3])    \
                 : "r"((a)[0]), "r"((a)[1]), "r"((a)[2]), "r"((a)[3]),       \
                   "r"((b)[0]), "r"((b)[1]))
#define CP_ASYNC16(dst, src)                                                 \
    asm volatile("cp.async.cg.shared.global [%0],[%1],16;" :: "r"(dst), "l"(src))
#define CP_COMMIT() asm volatile("cp.async.commit_group;")
#define CP_WAIT1()  asm volatile("cp.async.wait_group 1;")
#define CP_WAIT0()  asm volatile("cp.async.wait_group 0;")

// pack two fp32 -> f16x2 register (v1 in upper half, v0 in lower)
__device__ __forceinline__ uint32_t packh(float v0, float v1) {
    uint32_t r;
    asm("cvt.rn.f16x2.f32 %0,%1,%2;" : "=r"(r) : "f"(v1), "f"(v0));
    return r;
}
// hi/lo split of a pair: hi = fp16(v), lo = fp16(v - hi)
__device__ __forceinline__ void split2h(float v0, float v1,
                                        uint32_t& hi, uint32_t& lo) {
    __half h0 = __float2half_rn(v0), h1 = __float2half_rn(v1);
    hi = ((uint32_t)__half_as_ushort(h1) << 16) | __half_as_ushort(h0);
    lo = packh(v0 - __half2float(h0), v1 - __half2float(h1));
}

// --------------- fp32 -> fp16 conversions (single merged launch) -----------
#define N4X  (Bb * Nn * Cc / 4)
#define N4WI (3 * Cc * Cc / 4)
#define N4WO (Cc * Cc / 4)

__global__ __launch_bounds__(256) void cvt_all(const float4* __restrict__ x,
                                               const float4* __restrict__ wi,
                                               const float4* __restrict__ wo)
{
    int i = blockIdx.x * 256 + threadIdx.x;
    if (i < N4X) {                          // x -> single fp16
        float4 f = x[i];
        ((uint2*)g_x)[i] = make_uint2(packh(f.x, f.y), packh(f.z, f.w));
        return;
    }
    const float4* src;
    __half *hi, *lo;
    int j;
    if (i < N4X + N4WI)      { src = wi; hi = g_wih; lo = g_wil; j = i - N4X; }
    else if (i < N4X + N4WI + N4WO)
                             { src = wo; hi = g_woh; lo = g_wol; j = i - N4X - N4WI; }
    else return;
    float4 f = src[j];
    uint32_t h01, l01, h23, l23;
    split2h(f.x, f.y, h01, l01);
    split2h(f.z, f.w, h23, l23);
    ((uint2*)hi)[j] = make_uint2(h01, h23);
    ((uint2*)lo)[j] = make_uint2(l01, l23);
}

// ---------------------------------------------------------------------------
// fp16x2 TN GEMM (HMMA): C = A*W^T + bias ~= Ah*(Wh + Wl)
// CTA tile 128x128, BK=32, 3-stage cp.async, one sync/chunk, SW64 swizzle.
// Stage = A(8KB) + Wh(8KB) + Wl(8KB) = 24KB; 3 stages = 72KB; 2 CTAs/SM.
// 8 warps (4m x 2n), warp tile 32x64, 32 MMAs/chunk/warp (was 48).
// EPI=0: A=x, W=w_in; scatter q(single,scaled) / k,v (hi/lo).
// EPI=1: A=g_ao, W=w_out; fp32 out.
// ---------------------------------------------------------------------------
#define MATG 8192
#define GSTG (3 * MATG)              // 24576 B / stage
#define GSMEM (3 * GSTG)             // 73728 B

#define SWOFF(row, unit) ((uint32_t)((row) * 64 + (((unit) ^ (((row) >> 1) & 3)) << 4)))

template <int EPI>
__device__ __forceinline__ void tg_load(uint32_t sbase, int bm, int bn,
                                        int k0, int tid)
{
    const __half* A  = (EPI == 0) ? g_x : g_ao;
    const __half* Wh = (EPI == 0) ? g_wih : g_woh;
    const __half* Wl = (EPI == 0) ? g_wil : g_wol;
#pragma unroll
    for (int u = 0; u < 2; u++) {
        int idx = u * 256 + tid;          // 0..511
        int row = idx >> 2, un = idx & 3;
        uint32_t soff = SWOFF(row, un);
        size_t ga = (size_t)(bm + row) * 1024 + k0 + un * 8;
        size_t gw = (size_t)(bn + row) * 1024 + k0 + un * 8;
        CP_ASYNC16(sbase + 0 * MATG + soff, A + ga);
        CP_ASYNC16(sbase + 1 * MATG + soff, Wh + gw);
        CP_ASYNC16(sbase + 2 * MATG + soff, Wl + gw);
    }
}

template <int EPI>
__global__ __launch_bounds__(256, 2) void gemm_mma(const float* __restrict__ bias,
                                                   float* __restrict__ out)
{
    extern __shared__ __align__(16) char smem[];
    const uint32_t sm0 = (uint32_t)__cvta_generic_to_shared(smem);

    const int tid  = threadIdx.x;
    const int lane = tid & 31;
    const int wid  = tid >> 5;
    const int wm = (wid & 3) * 32;
    const int wn = (wid >> 2) * 64;
    const int bm = blockIdx.y * 128;
    const int bn = blockIdx.x * 128;

    const int lr = lane & 7, lq = lane >> 3;
    const int arow = wm + (lq & 1) * 8 + lr;
    const int sxA  = ((arow >> 1) & 3);
    const int aub  = (lq >> 1);
    const int brow = wn + (lane & 7) + ((lane >> 4) & 1) * 8;
    const int sxB  = ((brow >> 1) & 3);
    const int bub  = ((lane >> 3) & 1);

    float c[2][8][4];
#pragma unroll
    for (int im = 0; im < 2; im++)
#pragma unroll
        for (int jn = 0; jn < 8; jn++)
#pragma unroll
            for (int q = 0; q < 4; q++) c[im][jn][q] = 0.0f;

    tg_load<EPI>(sm0 + 0 * GSTG, bm, bn, 0, tid);
    CP_COMMIT();
    tg_load<EPI>(sm0 + 1 * GSTG, bm, bn, 32, tid);
    CP_COMMIT();

    for (int ch = 0; ch < 32; ch++) {
        if (ch < 31) CP_WAIT1(); else CP_WAIT0();
        __syncthreads();

        if (ch < 30) {
            tg_load<EPI>(sm0 + ((ch + 2) % 3) * GSTG, bm, bn, (ch + 2) * 32, tid);
            CP_COMMIT();
        }

        const uint32_t st = sm0 + (ch % 3) * GSTG;
        const uint32_t tA  = st;
        const uint32_t tBh = st + 1 * MATG, tBl = st + 2 * MATG;

#pragma unroll
        for (int ks = 0; ks < 2; ks++) {
            const uint32_t aup = (uint32_t)((((ks << 1) | aub) ^ sxA) << 4);
            const uint32_t bup = (uint32_t)((((ks << 1) | bub) ^ sxB) << 4);
            uint32_t aH[2][4];
#pragma unroll
            for (int im = 0; im < 2; im++) {
                uint32_t off = (uint32_t)((arow + im * 16) * 64) + aup;
                LDSM4(aH[im][0], aH[im][1], aH[im][2], aH[im][3], tA + off);
            }
#pragma unroll
            for (int jp = 0; jp < 2; jp++) {
                uint32_t bh[2][4], bl[2][4];
#pragma unroll
                for (int j = 0; j < 2; j++) {
                    int jn2 = jp * 2 + j;
                    uint32_t off = (uint32_t)((brow + jn2 * 16) * 64) + bup;
                    LDSM4(bh[j][0], bh[j][1], bh[j][2], bh[j][3], tBh + off);
                    LDSM4(bl[j][0], bl[j][1], bl[j][2], bl[j][3], tBl + off);
                }
                // 16 MMAs over 8 independent accumulators (dep distance 8)
#pragma unroll
                for (int j = 0; j < 2; j++)
#pragma unroll
                    for (int im = 0; im < 2; im++) {
                        MMA16816(c[im][2 * (jp * 2 + j)],     aH[im], &bh[j][0]);
                        MMA16816(c[im][2 * (jp * 2 + j) + 1], aH[im], &bh[j][2]);
                    }
#pragma unroll
                for (int j = 0; j < 2; j++)
#pragma unroll
                    for (int im = 0; im < 2; im++) {
                        MMA16816(c[im][2 * (jp * 2 + j)],     aH[im], &bl[j][0]);
                        MMA16816(c[im][2 * (jp * 2 + j) + 1], aH[im], &bl[j][2]);
                    }
            }
        }
    }

    // epilogue
#pragma unroll
    for (int im = 0; im < 2; im++) {
#pragma unroll
        for (int jn = 0; jn < 8; jn++) {
            int r0 = bm + wm + im * 16 + (lane >> 2);
            int cg = bn + wn + jn * 8 + 2 * (lane & 3);
            float b0 = bias[cg], b1 = bias[cg + 1];
#pragma unroll
            for (int half = 0; half < 2; half++) {
                int r = r0 + half * 8;
                float v0 = c[im][jn][half * 2 + 0] + b0;
                float v1 = c[im][jn][half * 2 + 1] + b1;
                if (EPI == 0) {
                    int b = r >> 10, nn = r & 1023;
                    int s = cg >> 10;
                    int h = (cg >> 6) & 15;
                    int d = cg & 63;
                    size_t idx = (((size_t)b * Hh + h) * Nn + nn) * Dd + d;
                    if (s == 0) {           // Q: single fp16, QK scale folded
                        *(uint32_t*)&g_q[idx] = packh(v0 * 0.125f, v1 * 0.125f);
                    } else {                // K/V: hi/lo
                        __half* hiA = (s == 1) ? g_kh : g_vh;
                        __half* loA = (s == 1) ? g_kl : g_vl;
                        uint32_t hp, lp;
                        split2h(v0, v1, hp, lp);
                        *(uint32_t*)&hiA[idx] = hp;
                        *(uint32_t*)&loA[idx] = lp;
                    }
                } else {
                    *(float2*)&out[(size_t)r * 1024 + cg] = make_float2(v0, v1);
                }
            }
        }
    }
}

// ---------------------------------------------------------------------------
// fp16x2 MMA flash attention (R11 64-key structure).
// S = Q*(Kh+Kl); O += P*(Vh+Vl); P packed single fp16.
// Smem: 2 KV stages (Kh,Kl,Vh,Vl @ 64x144 = 36864 each); Q (single, 18432)
// staged through the stage-1 region before the main loop. Total 73728.
// ---------------------------------------------------------------------------
#define ASTG 36864
#define AMAT 9216

__global__ __launch_bounds__(256, 1) void attn_mma()
{
    extern __shared__ __align__(16) char smem[];
    const uint32_t sm0 = (uint32_t)__cvta_generic_to_shared(smem);

    const int tid  = threadIdx.x;
    const int lane = tid & 31;
    const int wq   = tid >> 5;
    const int bh = blockIdx.y;
    const int q0 = blockIdx.x * 128;

    const __half* Qp  = g_q  + (size_t)bh * NDh;
    const __half* Khp = g_kh + (size_t)bh * NDh;
    const __half* Klp = g_kl + (size_t)bh * NDh;
    const __half* Vhp = g_vh + (size_t)bh * NDh;
    const __half* Vlp = g_vl + (size_t)bh * NDh;

    const uint32_t qbase = sm0 + ASTG;
#pragma unroll
    for (int u = 0; u < 4; u++) {          // Q single: 128 rows x 144B
        int r = u * 32 + (tid >> 3);
        int cc = tid & 7;
        CP_ASYNC16(qbase + r * 144 + cc * 16,
                   Qp + (size_t)(q0 + r) * 64 + cc * 8);
    }
    CP_COMMIT();
    {
#pragma unroll
        for (int u = 0; u < 8; u++) {
            const __half* mp = (u < 2) ? Khp : (u < 4) ? Klp
                               : (u < 6) ? Vhp : Vlp;
            int r = (u & 1) * 32 + (tid >> 3);
            int cc = tid & 7;
            CP_ASYNC16(sm0 + (u >> 1) * AMAT + r * 144 + cc * 16,
                       mp + (size_t)r * 64 + cc * 8);
        }
        CP_COMMIT();
    }
    CP_WAIT1();
    __syncthreads();

    uint32_t qf[4][4];
    {
        const int lr = lane & 7, lq = lane >> 3;
        uint32_t qa = qbase + (uint32_t)((wq * 16 + (lq & 1) * 8 + lr) * 144
                                         + (lq >> 1) * 16);
#pragma unroll
        for (int ks = 0; ks < 4; ks++)
            LDSM4(qf[ks][0], qf[ks][1], qf[ks][2], qf[ks][3], qa + ks * 32);
    }
    __syncthreads();       // Q smem region free (stage 1 overlaps it)

    float o[8][4];
    float mrow[2] = {-1e30f, -1e30f}, lrow[2] = {0.0f, 0.0f};
#pragma unroll
    for (int j = 0; j < 8; j++)
#pragma unroll
        for (int q = 0; q < 4; q++) o[j][q] = 0.0f;

    for (int t = 0; t < 16; t++) {
        if (t < 15) {
            uint32_t nb = sm0 + ((t + 1) & 1) * ASTG;
            int key0 = (t + 1) * 64;
#pragma unroll
            for (int u = 0; u < 8; u++) {
                const __half* mp = (u < 2) ? Khp : (u < 4) ? Klp
                                   : (u < 6) ? Vhp : Vlp;
                int r = (u & 1) * 32 + (tid >> 3);
                int cc = tid & 7;
                CP_ASYNC16(nb + (u >> 1) * AMAT + r * 144 + cc * 16,
                           mp + (size_t)(key0 + r) * 64 + cc * 8);
            }
            CP_COMMIT();
            CP_WAIT1();
        } else {
            CP_WAIT0();
        }
        __syncthreads();

        const uint32_t st = sm0 + (t & 1) * ASTG;

        // ---- S = Q K^T (2 MMAs per 16x16 tile) ---------------------------
        float s[8][4];
#pragma unroll
        for (int j = 0; j < 8; j++)
#pragma unroll
            for (int q = 0; q < 4; q++) s[j][q] = 0.0f;

        const uint32_t kaddr = st + (uint32_t)(((lane & 7) + ((lane >> 4) & 1) * 8) * 144
                                               + ((lane >> 3) & 1) * 16);
#pragma unroll
        for (int ks = 0; ks < 4; ks++) {
            uint32_t kh[4][4], kl[4][4];
#pragma unroll
            for (int jn2 = 0; jn2 < 4; jn2++) {
                uint32_t off = kaddr + (uint32_t)(jn2 * 16 * 144 + ks * 32);
                LDSM4(kh[jn2][0], kh[jn2][1], kh[jn2][2], kh[jn2][3], off);
                LDSM4(kl[jn2][0], kl[jn2][1], kl[jn2][2], kl[jn2][3], off + AMAT);
            }
#pragma unroll
            for (int jn2 = 0; jn2 < 4; jn2++) {
                MMA16816(s[2 * jn2],     qf[ks], &kh[jn2][0]);
                MMA16816(s[2 * jn2],     qf[ks], &kl[jn2][0]);
                MMA16816(s[2 * jn2 + 1], qf[ks], &kh[jn2][2]);
                MMA16816(s[2 * jn2 + 1], qf[ks], &kl[jn2][2]);
            }
        }

        // ---- online softmax ----------------------------------------------
#pragma unroll
        for (int r = 0; r < 2; r++) {
            float mx = -1e30f;
#pragma unroll
            for (int j = 0; j < 8; j++)
                mx = fmaxf(mx, fmaxf(s[j][2 * r], s[j][2 * r + 1]));
            mx = fmaxf(mx, __shfl_xor_sync(0xffffffffu, mx, 1));
            mx = fmaxf(mx, __shfl_xor_sync(0xffffffffu, mx, 2));
            float mnew = fmaxf(mrow[r], mx);
            float corr = __expf(mrow[r] - mnew);
            float sum = 0.0f;
#pragma unroll
            for (int j = 0; j < 8; j++) {
                s[j][2 * r]     = __expf(s[j][2 * r]     - mnew);
                s[j][2 * r + 1] = __expf(s[j][2 * r + 1] - mnew);
                sum += s[j][2 * r] + s[j][2 * r + 1];
            }
            sum += __shfl_xor_sync(0xffffffffu, sum, 1);
            sum += __shfl_xor_sync(0xffffffffu, sum, 2);
            lrow[r] = lrow[r] * corr + sum;
            mrow[r] = mnew;
#pragma unroll
            for (int j = 0; j < 8; j++) {
                o[j][2 * r]     *= corr;
                o[j][2 * r + 1] *= corr;
            }
        }

        // ---- O += P V (P single fp16) ------------------------------------
        const uint32_t vaddr = st + 2 * AMAT
            + (uint32_t)((lane & 15) * 144 + (lane >> 4) * 16);
#pragma unroll
        for (int ks2 = 0; ks2 < 4; ks2++) {
            uint32_t pa[4];
            float* s0 = s[2 * ks2];
            float* s1 = s[2 * ks2 + 1];
            pa[0] = packh(s0[0], s0[1]);
            pa[1] = packh(s0[2], s0[3]);
            pa[2] = packh(s1[0], s1[1]);
            pa[3] = packh(s1[2], s1[3]);

            uint32_t vrow = vaddr + (uint32_t)(ks2 * 16 * 144);
#pragma unroll
            for (int jd2 = 0; jd2 < 4; jd2++) {
                uint32_t vh[4], vl[4];
                uint32_t off = vrow + (uint32_t)(jd2 * 32);
                LDSM4T(vh[0], vh[1], vh[2], vh[3], off);
                LDSM4T(vl[0], vl[1], vl[2], vl[3], off + AMAT);
                MMA16816(o[2 * jd2],     pa, &vh[0]);
                MMA16816(o[2 * jd2],     pa, &vl[0]);
                MMA16816(o[2 * jd2 + 1], pa, &vh[2]);
                MMA16816(o[2 * jd2 + 1], pa, &vl[2]);
            }
        }
        __syncthreads();
    }

    // ---- normalize + write single-fp16 attention output [B,N,C] -----------
    const int b = bh >> 4, h = bh & 15;
    const int G = lane >> 2, T = lane & 3;
#pragma unroll
    for (int r = 0; r < 2; r++) {
        float inv = 1.0f / lrow[r];
        int row = q0 + wq * 16 + G + r * 8;
        size_t base = ((size_t)b * Nn + row) * Cc + h * 64;
#pragma unroll
        for (int jd = 0; jd < 8; jd++) {
            float v0 = o[jd][2 * r] * inv;
            float v1 = o[jd][2 * r + 1] * inv;
            int col = jd * 8 + 2 * T;
            *(uint32_t*)&g_ao[base + col] = packh(v0, v1);
        }
    }
}

// ---------------------------------------------------------------------------
extern "C" void kernel_launch(void* const* d_in, const int* in_sizes, int n_in,
                              void* d_out, int out_size)
{
    const float* x     = (const float*)d_in[0];
    const float* w_in  = (const float*)d_in[1];
    const float* b_in  = (const float*)d_in[2];
    const float* w_out = (const float*)d_in[3];
    const float* b_out = (const float*)d_in[4];
    float* out = (float*)d_out;

    cudaFuncSetAttribute(gemm_mma<0>,
                         cudaFuncAttributeMaxDynamicSharedMemorySize, GSMEM);
    cudaFuncSetAttribute(gemm_mma<1>,
                         cudaFuncAttributeMaxDynamicSharedMemorySize, GSMEM);
    cudaFuncSetAttribute(attn_mma,
                         cudaFuncAttributeMaxDynamicSharedMemorySize, 2 * ASTG);

    // merged fp32 -> fp16 conversions (x single; w_in / w_out hi+lo)
    cvt_all<<<(N4X + N4WI + N4WO + 255) / 256, 256>>>(
        (const float4*)x, (const float4*)w_in, (const float4*)w_out);

    // QKV projection: 8192 x 3072 x 1024 -> q (single, scaled), k/v (hi/lo)
    gemm_mma<0><<<dim3(24, 64), 256, GSMEM>>>(b_in, nullptr);
    // Attention: 8 q-tiles x 128 (b,h)
    attn_mma<<<dim3(8, 128), 256, 2 * ASTG>>>();
    // Output projection: 8192 x 1024 x 1024
    gemm_mma<1><<<dim3(8, 64), 256, GSMEM>>>(b_out, out);
}

// round 15
// speedup vs baseline: 1.5971x; 1.5971x over previous
#include <cuda_runtime.h>
#include <cuda_fp16.h>
#include <cstdint>

#define Bb 8
#define Nn 1024
#define Cc 1024
#define Hh 16
#define Dd 64
#define NDh (Nn * Dd)

// ---------------- scratch (device globals; allocation-free) ----------------
__device__ __align__(16) __half g_x[Bb * Nn * Cc];                // x, fp16
__device__ __align__(16) __half g_wih[3 * Cc * Cc], g_wil[3 * Cc * Cc];
__device__ __align__(16) __half g_woh[Cc * Cc], g_wol[Cc * Cc];
__device__ __align__(16) __half g_q[Bb * Hh * NDh];               // q single (scaled)
__device__ __align__(16) __half g_kh[Bb * Hh * NDh], g_kl[Bb * Hh * NDh];
__device__ __align__(16) __half g_vh[Bb * Hh * NDh], g_vl[Bb * Hh * NDh];
__device__ __align__(16) __half g_ao[Bb * Nn * Cc];               // attn out single

// ---------------------------- PTX helpers ----------------------------------
#define LDSM4(r0, r1, r2, r3, addr)                                          \
    asm volatile("ldmatrix.sync.aligned.m8n8.x4.shared.b16 {%0,%1,%2,%3},[%4];" \
                 : "=r"(r0), "=r"(r1), "=r"(r2), "=r"(r3) : "r"(addr))
#define LDSM4T(r0, r1, r2, r3, addr)                                         \
    asm volatile("ldmatrix.sync.aligned.m8n8.x4.trans.shared.b16 {%0,%1,%2,%3},[%4];" \
                 : "=r"(r0), "=r"(r1), "=r"(r2), "=r"(r3) : "r"(addr))
#define MMA16816(c, a, b)                                                    \
    asm volatile("mma.sync.aligned.m16n8k16.row.col.f32.f16.f16.f32 "        \
                 "{%0,%1,%2,%3},{%4,%5,%6,%7},{%8,%9},{%0,%1,%2,%3};"        \
                 : "+f"((c)[0]), "+f"((c)[1]), "+f"((c)[2]), "+f"((c)[3])    \
                 : "r"((a)[0]), "r"((a)[1]), "r"((a)[2]), "r"((a)[3]),       \
                   "r"((b)[0]), "r"((b)[1]))
#define CP_ASYNC16(dst, src)                                                 \
    asm volatile("cp.async.cg.shared.global [%0],[%1],16;" :: "r"(dst), "l"(src))
#define CP_COMMIT() asm volatile("cp.async.commit_group;")
#define CP_WAIT1()  asm volatile("cp.async.wait_group 1;")
#define CP_WAIT0()  asm volatile("cp.async.wait_group 0;")

// pack two fp32 -> f16x2 register (v1 in upper half, v0 in lower)
__device__ __forceinline__ uint32_t packh(float v0, float v1) {
    uint32_t r;
    asm("cvt.rn.f16x2.f32 %0,%1,%2;" : "=r"(r) : "f"(v1), "f"(v0));
    return r;
}
// hi/lo split of a pair: hi = fp16(v), lo = fp16(v - hi)
__device__ __forceinline__ void split2h(float v0, float v1,
                                        uint32_t& hi, uint32_t& lo) {
    __half h0 = __float2half_rn(v0), h1 = __float2half_rn(v1);
    hi = ((uint32_t)__half_as_ushort(h1) << 16) | __half_as_ushort(h0);
    lo = packh(v0 - __half2float(h0), v1 - __half2float(h1));
}

// --------------- fp32 -> fp16 conversions (single merged launch) -----------
#define N4X  (Bb * Nn * Cc / 4)
#define N4WI (3 * Cc * Cc / 4)
#define N4WO (Cc * Cc / 4)

__global__ __launch_bounds__(256) void cvt_all(const float4* __restrict__ x,
                                               const float4* __restrict__ wi,
                                               const float4* __restrict__ wo)
{
    int i = blockIdx.x * 256 + threadIdx.x;
    if (i < N4X) {                          // x -> single fp16
        float4 f = x[i];
        ((uint2*)g_x)[i] = make_uint2(packh(f.x, f.y), packh(f.z, f.w));
        return;
    }
    const float4* src;
    __half *hi, *lo;
    int j;
    if (i < N4X + N4WI)      { src = wi; hi = g_wih; lo = g_wil; j = i - N4X; }
    else if (i < N4X + N4WI + N4WO)
                             { src = wo; hi = g_woh; lo = g_wol; j = i - N4X - N4WI; }
    else return;
    float4 f = src[j];
    uint32_t h01, l01, h23, l23;
    split2h(f.x, f.y, h01, l01);
    split2h(f.z, f.w, h23, l23);
    ((uint2*)hi)[j] = make_uint2(h01, h23);
    ((uint2*)lo)[j] = make_uint2(l01, l23);
}

// ---------------------------------------------------------------------------
// fp16x2 TN GEMM (HMMA): C = A*W^T + bias ~= Ah*(Wh + Wl)
// CTA tile 128x128, BK=32, 3-stage cp.async, one sync/chunk, SW64 swizzle.
// Stage = A(8KB) + Wh(8KB) + Wl(8KB) = 24KB; 3 stages = 72KB; 2 CTAs/SM.
// 8 warps (4m x 2n), warp tile 32x64, 32 MMAs/chunk/warp.
// ---------------------------------------------------------------------------
#define MATG 8192
#define GSTG (3 * MATG)              // 24576 B / stage
#define GSMEM (3 * GSTG)             // 73728 B

#define SWOFF(row, unit) ((uint32_t)((row) * 64 + (((unit) ^ (((row) >> 1) & 3)) << 4)))

template <int EPI>
__device__ __forceinline__ void tg_load(uint32_t sbase, int bm, int bn,
                                        int k0, int tid)
{
    const __half* A  = (EPI == 0) ? g_x : g_ao;
    const __half* Wh = (EPI == 0) ? g_wih : g_woh;
    const __half* Wl = (EPI == 0) ? g_wil : g_wol;
#pragma unroll
    for (int u = 0; u < 2; u++) {
        int idx = u * 256 + tid;          // 0..511
        int row = idx >> 2, un = idx & 3;
        uint32_t soff = SWOFF(row, un);
        size_t ga = (size_t)(bm + row) * 1024 + k0 + un * 8;
        size_t gw = (size_t)(bn + row) * 1024 + k0 + un * 8;
        CP_ASYNC16(sbase + 0 * MATG + soff, A + ga);
        CP_ASYNC16(sbase + 1 * MATG + soff, Wh + gw);
        CP_ASYNC16(sbase + 2 * MATG + soff, Wl + gw);
    }
}

template <int EPI>
__global__ __launch_bounds__(256, 2) void gemm_mma(const float* __restrict__ bias,
                                                   float* __restrict__ out)
{
    extern __shared__ __align__(16) char smem[];
    const uint32_t sm0 = (uint32_t)__cvta_generic_to_shared(smem);

    const int tid  = threadIdx.x;
    const int lane = tid & 31;
    const int wid  = tid >> 5;
    const int wm = (wid & 3) * 32;
    const int wn = (wid >> 2) * 64;
    const int bm = blockIdx.y * 128;
    const int bn = blockIdx.x * 128;

    const int lr = lane & 7, lq = lane >> 3;
    const int arow = wm + (lq & 1) * 8 + lr;
    const int sxA  = ((arow >> 1) & 3);
    const int aub  = (lq >> 1);
    const int brow = wn + (lane & 7) + ((lane >> 4) & 1) * 8;
    const int sxB  = ((brow >> 1) & 3);
    const int bub  = ((lane >> 3) & 1);

    float c[2][8][4];
#pragma unroll
    for (int im = 0; im < 2; im++)
#pragma unroll
        for (int jn = 0; jn < 8; jn++)
#pragma unroll
            for (int q = 0; q < 4; q++) c[im][jn][q] = 0.0f;

    tg_load<EPI>(sm0 + 0 * GSTG, bm, bn, 0, tid);
    CP_COMMIT();
    tg_load<EPI>(sm0 + 1 * GSTG, bm, bn, 32, tid);
    CP_COMMIT();

    for (int ch = 0; ch < 32; ch++) {
        if (ch < 31) CP_WAIT1(); else CP_WAIT0();
        __syncthreads();

        if (ch < 30) {
            tg_load<EPI>(sm0 + ((ch + 2) % 3) * GSTG, bm, bn, (ch + 2) * 32, tid);
            CP_COMMIT();
        }

        const uint32_t st = sm0 + (ch % 3) * GSTG;
        const uint32_t tA  = st;
        const uint32_t tBh = st + 1 * MATG, tBl = st + 2 * MATG;

#pragma unroll
        for (int ks = 0; ks < 2; ks++) {
            const uint32_t aup = (uint32_t)((((ks << 1) | aub) ^ sxA) << 4);
            const uint32_t bup = (uint32_t)((((ks << 1) | bub) ^ sxB) << 4);
            uint32_t aH[2][4];
#pragma unroll
            for (int im = 0; im < 2; im++) {
                uint32_t off = (uint32_t)((arow + im * 16) * 64) + aup;
                LDSM4(aH[im][0], aH[im][1], aH[im][2], aH[im][3], tA + off);
            }
#pragma unroll
            for (int jp = 0; jp < 2; jp++) {
                uint32_t bh[2][4], bl[2][4];
#pragma unroll
                for (int j = 0; j < 2; j++) {
                    int jn2 = jp * 2 + j;
                    uint32_t off = (uint32_t)((brow + jn2 * 16) * 64) + bup;
                    LDSM4(bh[j][0], bh[j][1], bh[j][2], bh[j][3], tBh + off);
                    LDSM4(bl[j][0], bl[j][1], bl[j][2], bl[j][3], tBl + off);
                }
                // 16 MMAs over 8 independent accumulators (dep distance 8)
#pragma unroll
                for (int j = 0; j < 2; j++)
#pragma unroll
                    for (int im = 0; im < 2; im++) {
                        MMA16816(c[im][2 * (jp * 2 + j)],     aH[im], &bh[j][0]);
                        MMA16816(c[im][2 * (jp * 2 + j) + 1], aH[im], &bh[j][2]);
                    }
#pragma unroll
                for (int j = 0; j < 2; j++)
#pragma unroll
                    for (int im = 0; im < 2; im++) {
                        MMA16816(c[im][2 * (jp * 2 + j)],     aH[im], &bl[j][0]);
                        MMA16816(c[im][2 * (jp * 2 + j) + 1], aH[im], &bl[j][2]);
                    }
            }
        }
    }

    // epilogue
#pragma unroll
    for (int im = 0; im < 2; im++) {
#pragma unroll
        for (int jn = 0; jn < 8; jn++) {
            int r0 = bm + wm + im * 16 + (lane >> 2);
            int cg = bn + wn + jn * 8 + 2 * (lane & 3);
            float b0 = bias[cg], b1 = bias[cg + 1];
#pragma unroll
            for (int half = 0; half < 2; half++) {
                int r = r0 + half * 8;
                float v0 = c[im][jn][half * 2 + 0] + b0;
                float v1 = c[im][jn][half * 2 + 1] + b1;
                if (EPI == 0) {
                    int b = r >> 10, nn = r & 1023;
                    int s = cg >> 10;
                    int h = (cg >> 6) & 15;
                    int d = cg & 63;
                    size_t idx = (((size_t)b * Hh + h) * Nn + nn) * Dd + d;
                    if (s == 0) {           // Q: single fp16, QK scale folded
                        *(uint32_t*)&g_q[idx] = packh(v0 * 0.125f, v1 * 0.125f);
                    } else {                // K/V: hi/lo
                        __half* hiA = (s == 1) ? g_kh : g_vh;
                        __half* loA = (s == 1) ? g_kl : g_vl;
                        uint32_t hp, lp;
                        split2h(v0, v1, hp, lp);
                        *(uint32_t*)&hiA[idx] = hp;
                        *(uint32_t*)&loA[idx] = lp;
                    }
                } else {
                    *(float2*)&out[(size_t)r * 1024 + cg] = make_float2(v0, v1);
                }
            }
        }
    }
}

// ---------------------------------------------------------------------------
// fp16x2 MMA flash attention, 64-key tiles, NOW 2 CTAs/SM (147KB smem/SM).
// S = Q*(Kh+Kl); O += P*(Vh+Vl); P packed single fp16.
// Smem: 2 KV stages (Kh,Kl,Vh,Vl @ 64x144 = 36864 each); Q (single, 18432)
// staged through the stage-1 region before the main loop. Total 73728.
// ---------------------------------------------------------------------------
#define ASTG 36864
#define AMAT 9216

__global__ __launch_bounds__(256, 2) void attn_mma()
{
    extern __shared__ __align__(16) char smem[];
    const uint32_t sm0 = (uint32_t)__cvta_generic_to_shared(smem);

    const int tid  = threadIdx.x;
    const int lane = tid & 31;
    const int wq   = tid >> 5;
    const int bh = blockIdx.y;
    const int q0 = blockIdx.x * 128;

    const __half* Qp  = g_q  + (size_t)bh * NDh;
    const __half* Khp = g_kh + (size_t)bh * NDh;
    const __half* Klp = g_kl + (size_t)bh * NDh;
    const __half* Vhp = g_vh + (size_t)bh * NDh;
    const __half* Vlp = g_vl + (size_t)bh * NDh;

    const uint32_t qbase = sm0 + ASTG;
#pragma unroll
    for (int u = 0; u < 4; u++) {          // Q single: 128 rows x 144B
        int r = u * 32 + (tid >> 3);
        int cc = tid & 7;
        CP_ASYNC16(qbase + r * 144 + cc * 16,
                   Qp + (size_t)(q0 + r) * 64 + cc * 8);
    }
    CP_COMMIT();
    {
#pragma unroll
        for (int u = 0; u < 8; u++) {
            const __half* mp = (u < 2) ? Khp : (u < 4) ? Klp
                               : (u < 6) ? Vhp : Vlp;
            int r = (u & 1) * 32 + (tid >> 3);
            int cc = tid & 7;
            CP_ASYNC16(sm0 + (u >> 1) * AMAT + r * 144 + cc * 16,
                       mp + (size_t)r * 64 + cc * 8);
        }
        CP_COMMIT();
    }
    CP_WAIT1();
    __syncthreads();

    uint32_t qf[4][4];
    {
        const int lr = lane & 7, lq = lane >> 3;
        uint32_t qa = qbase + (uint32_t)((wq * 16 + (lq & 1) * 8 + lr) * 144
                                         + (lq >> 1) * 16);
#pragma unroll
        for (int ks = 0; ks < 4; ks++)
            LDSM4(qf[ks][0], qf[ks][1], qf[ks][2], qf[ks][3], qa + ks * 32);
    }
    __syncthreads();       // Q smem region free (stage 1 overlaps it)

    float o[8][4];
    float mrow[2] = {-1e30f, -1e30f}, lrow[2] = {0.0f, 0.0f};
#pragma unroll
    for (int j = 0; j < 8; j++)
#pragma unroll
        for (int q = 0; q < 4; q++) o[j][q] = 0.0f;

    for (int t = 0; t < 16; t++) {
        if (t < 15) {
            uint32_t nb = sm0 + ((t + 1) & 1) * ASTG;
            int key0 = (t + 1) * 64;
#pragma unroll
            for (int u = 0; u < 8; u++) {
                const __half* mp = (u < 2) ? Khp : (u < 4) ? Klp
                                   : (u < 6) ? Vhp : Vlp;
                int r = (u & 1) * 32 + (tid >> 3);
                int cc = tid & 7;
                CP_ASYNC16(nb + (u >> 1) * AMAT + r * 144 + cc * 16,
                           mp + (size_t)(key0 + r) * 64 + cc * 8);
            }
            CP_COMMIT();
            CP_WAIT1();
        } else {
            CP_WAIT0();
        }
        __syncthreads();

        const uint32_t st = sm0 + (t & 1) * ASTG;

        // ---- S = Q K^T (2 MMAs per 16x16 tile) ---------------------------
        float s[8][4];
#pragma unroll
        for (int j = 0; j < 8; j++)
#pragma unroll
            for (int q = 0; q < 4; q++) s[j][q] = 0.0f;

        const uint32_t kaddr = st + (uint32_t)(((lane & 7) + ((lane >> 4) & 1) * 8) * 144
                                               + ((lane >> 3) & 1) * 16);
#pragma unroll
        for (int ks = 0; ks < 4; ks++) {
            uint32_t kh[4][4], kl[4][4];
#pragma unroll
            for (int jn2 = 0; jn2 < 4; jn2++) {
                uint32_t off = kaddr + (uint32_t)(jn2 * 16 * 144 + ks * 32);
                LDSM4(kh[jn2][0], kh[jn2][1], kh[jn2][2], kh[jn2][3], off);
                LDSM4(kl[jn2][0], kl[jn2][1], kl[jn2][2], kl[jn2][3], off + AMAT);
            }
#pragma unroll
            for (int jn2 = 0; jn2 < 4; jn2++) {
                MMA16816(s[2 * jn2],     qf[ks], &kh[jn2][0]);
                MMA16816(s[2 * jn2],     qf[ks], &kl[jn2][0]);
                MMA16816(s[2 * jn2 + 1], qf[ks], &kh[jn2][2]);
                MMA16816(s[2 * jn2 + 1], qf[ks], &kl[jn2][2]);
            }
        }

        // ---- online softmax ----------------------------------------------
#pragma unroll
        for (int r = 0; r < 2; r++) {
            float mx = -1e30f;
#pragma unroll
            for (int j = 0; j < 8; j++)
                mx = fmaxf(mx, fmaxf(s[j][2 * r], s[j][2 * r + 1]));
            mx = fmaxf(mx, __shfl_xor_sync(0xffffffffu, mx, 1));
            mx = fmaxf(mx, __shfl_xor_sync(0xffffffffu, mx, 2));
            float mnew = fmaxf(mrow[r], mx);
            float corr = __expf(mrow[r] - mnew);
            float sum = 0.0f;
#pragma unroll
            for (int j = 0; j < 8; j++) {
                s[j][2 * r]     = __expf(s[j][2 * r]     - mnew);
                s[j][2 * r + 1] = __expf(s[j][2 * r + 1] - mnew);
                sum += s[j][2 * r] + s[j][2 * r + 1];
            }
            sum += __shfl_xor_sync(0xffffffffu, sum, 1);
            sum += __shfl_xor_sync(0xffffffffu, sum, 2);
            lrow[r] = lrow[r] * corr + sum;
            mrow[r] = mnew;
#pragma unroll
            for (int j = 0; j < 8; j++) {
                o[j][2 * r]     *= corr;
                o[j][2 * r + 1] *= corr;
            }
        }

        // ---- O += P V (P single fp16) ------------------------------------
        const uint32_t vaddr = st + 2 * AMAT
            + (uint32_t)((lane & 15) * 144 + (lane >> 4) * 16);
#pragma unroll
        for (int ks2 = 0; ks2 < 4; ks2++) {
            uint32_t pa[4];
            float* s0 = s[2 * ks2];
            float* s1 = s[2 * ks2 + 1];
            pa[0] = packh(s0[0], s0[1]);
            pa[1] = packh(s0[2], s0[3]);
            pa[2] = packh(s1[0], s1[1]);
            pa[3] = packh(s1[2], s1[3]);

            uint32_t vrow = vaddr + (uint32_t)(ks2 * 16 * 144);
#pragma unroll
            for (int jd2 = 0; jd2 < 4; jd2++) {
                uint32_t vh[4], vl[4];
                uint32_t off = vrow + (uint32_t)(jd2 * 32);
                LDSM4T(vh[0], vh[1], vh[2], vh[3], off);
                LDSM4T(vl[0], vl[1], vl[2], vl[3], off + AMAT);
                MMA16816(o[2 * jd2],     pa, &vh[0]);
                MMA16816(o[2 * jd2],     pa, &vl[0]);
                MMA16816(o[2 * jd2 + 1], pa, &vh[2]);
                MMA16816(o[2 * jd2 + 1], pa, &vl[2]);
            }
        }
        __syncthreads();
    }

    // ---- normalize + write single-fp16 attention output [B,N,C] -----------
    const int b = bh >> 4, h = bh & 15;
    const int G = lane >> 2, T = lane & 3;
#pragma unroll
    for (int r = 0; r < 2; r++) {
        float inv = 1.0f / lrow[r];
        int row = q0 + wq * 16 + G + r * 8;
        size_t base = ((size_t)b * Nn + row) * Cc + h * 64;
#pragma unroll
        for (int jd = 0; jd < 8; jd++) {
            float v0 = o[jd][2 * r] * inv;
            float v1 = o[jd][2 * r + 1] * inv;
            int col = jd * 8 + 2 * T;
            *(uint32_t*)&g_ao[base + col] = packh(v0, v1);
        }
    }
}

// ---------------------------------------------------------------------------
extern "C" void kernel_launch(void* const* d_in, const int* in_sizes, int n_in,
                              void* d_out, int out_size)
{
    const float* x     = (const float*)d_in[0];
    const float* w_in  = (const float*)d_in[1];
    const float* b_in  = (const float*)d_in[2];
    const float* w_out = (const float*)d_in[3];
    const float* b_out = (const float*)d_in[4];
    float* out = (float*)d_out;

    cudaFuncSetAttribute(gemm_mma<0>,
                         cudaFuncAttributeMaxDynamicSharedMemorySize, GSMEM);
    cudaFuncSetAttribute(gemm_mma<1>,
                         cudaFuncAttributeMaxDynamicSharedMemorySize, GSMEM);
    cudaFuncSetAttribute(attn_mma,
                         cudaFuncAttributeMaxDynamicSharedMemorySize, 2 * ASTG);

    // merged fp32 -> fp16 conversions (x single; w_in / w_out hi+lo)
    cvt_all<<<(N4X + N4WI + N4WO + 255) / 256, 256>>>(
        (const float4*)x, (const float4*)w_in, (const float4*)w_out);

    // QKV projection: 8192 x 3072 x 1024 -> q (single, scaled), k/v (hi/lo)
    gemm_mma<0><<<dim3(24, 64), 256, GSMEM>>>(b_in, nullptr);
    // Attention: 8 q-tiles x 128 (b,h), 2 CTAs/SM
    attn_mma<<<dim3(8, 128), 256, 2 * ASTG>>>();
    // Output projection: 8192 x 1024 x 1024
    gemm_mma<1><<<dim3(8, 64), 256, GSMEM>>>(b_out, out);
}

// round 16
// speedup vs baseline: 1.6145x; 1.0109x over previous
#include <cuda_runtime.h>
#include <cuda_fp16.h>
#include <cstdint>

#define Bb 8
#define Nn 1024
#define Cc 1024
#define Hh 16
#define Dd 64
#define NDh (Nn * Dd)

// ---------------- scratch (device globals; allocation-free) ----------------
__device__ __align__(16) __half g_x[Bb * Nn * Cc];                // x, fp16
__device__ __align__(16) __half g_wih[3 * Cc * Cc], g_wil[3 * Cc * Cc];
__device__ __align__(16) __half g_woh[Cc * Cc], g_wol[Cc * Cc];
__device__ __align__(16) __half g_q[Bb * Hh * NDh];               // q single (scaled)
__device__ __align__(16) __half g_kh[Bb * Hh * NDh], g_kl[Bb * Hh * NDh];
__device__ __align__(16) __half g_vh[Bb * Hh * NDh], g_vl[Bb * Hh * NDh];
__device__ __align__(16) __half g_ao[Bb * Nn * Cc];               // attn out single

// ---------------------------- PTX helpers ----------------------------------
#define LDSM4(r0, r1, r2, r3, addr)                                          \
    asm volatile("ldmatrix.sync.aligned.m8n8.x4.shared.b16 {%0,%1,%2,%3},[%4];" \
                 : "=r"(r0), "=r"(r1), "=r"(r2), "=r"(r3) : "r"(addr))
#define LDSM4T(r0, r1, r2, r3, addr)                                         \
    asm volatile("ldmatrix.sync.aligned.m8n8.x4.trans.shared.b16 {%0,%1,%2,%3},[%4];" \
                 : "=r"(r0), "=r"(r1), "=r"(r2), "=r"(r3) : "r"(addr))
#define MMA16816(c, a, b)                                                    \
    asm volatile("mma.sync.aligned.m16n8k16.row.col.f32.f16.f16.f32 "        \
                 "{%0,%1,%2,%3},{%4,%5,%6,%7},{%8,%9},{%0,%1,%2,%3};"        \
                 : "+f"((c)[0]), "+f"((c)[1]), "+f"((c)[2]), "+f"((c)[3])    \
                 : "r"((a)[0]), "r"((a)[1]), "r"((a)[2]), "r"((a)[3]),       \
                   "r"((b)[0]), "r"((b)[1]))
#define CP_ASYNC16(dst, src)                                                 \
    asm volatile("cp.async.cg.shared.global [%0],[%1],16;" :: "r"(dst), "l"(src))
#define CP_COMMIT() asm volatile("cp.async.commit_group;")
#define CP_WAIT2()  asm volatile("cp.async.wait_group 2;")
#define CP_WAIT1()  asm volatile("cp.async.wait_group 1;")
#define CP_WAIT0()  asm volatile("cp.async.wait_group 0;")

// pack two fp32 -> f16x2 register (v1 in upper half, v0 in lower)
__device__ __forceinline__ uint32_t packh(float v0, float v1) {
    uint32_t r;
    asm("cvt.rn.f16x2.f32 %0,%1,%2;" : "=r"(r) : "f"(v1), "f"(v0));
    return r;
}
// hi/lo split of a pair: hi = fp16(v), lo = fp16(v - hi)
__device__ __forceinline__ void split2h(float v0, float v1,
                                        uint32_t& hi, uint32_t& lo) {
    __half h0 = __float2half_rn(v0), h1 = __float2half_rn(v1);
    hi = ((uint32_t)__half_as_ushort(h1) << 16) | __half_as_ushort(h0);
    lo = packh(v0 - __half2float(h0), v1 - __half2float(h1));
}

// --------------- fp32 -> fp16 conversions (single merged launch) -----------
#define N4X  (Bb * Nn * Cc / 4)
#define N4WI (3 * Cc * Cc / 4)
#define N4WO (Cc * Cc / 4)

__global__ __launch_bounds__(256) void cvt_all(const float4* __restrict__ x,
                                               const float4* __restrict__ wi,
                                               const float4* __restrict__ wo)
{
    int i = blockIdx.x * 256 + threadIdx.x;
    if (i < N4X) {                          // x -> single fp16
        float4 f = x[i];
        ((uint2*)g_x)[i] = make_uint2(packh(f.x, f.y), packh(f.z, f.w));
        return;
    }
    const float4* src;
    __half *hi, *lo;
    int j;
    if (i < N4X + N4WI)      { src = wi; hi = g_wih; lo = g_wil; j = i - N4X; }
    else if (i < N4X + N4WI + N4WO)
                             { src = wo; hi = g_woh; lo = g_wol; j = i - N4X - N4WI; }
    else return;
    float4 f = src[j];
    uint32_t h01, l01, h23, l23;
    split2h(f.x, f.y, h01, l01);
    split2h(f.z, f.w, h23, l23);
    ((uint2*)hi)[j] = make_uint2(h01, h23);
    ((uint2*)lo)[j] = make_uint2(l01, l23);
}

// ---------------------------------------------------------------------------
// fp16x2 TN GEMM (HMMA): C = A*W^T + bias ~= Ah*(Wh + Wl)
// CTA tile 128x128, BK=32, 4-STAGE cp.async ring (prefetch distance 2),
// one sync/chunk, SW64 swizzle. Stage 24KB; 4 stages = 96KB; 2 CTAs/SM.
// 8 warps (4m x 2n), warp tile 32x64, 32 MMAs/chunk/warp.
// ---------------------------------------------------------------------------
#define MATG 8192
#define GSTG (3 * MATG)              // 24576 B / stage
#define GSMEM (4 * GSTG)             // 98304 B

#define SWOFF(row, unit) ((uint32_t)((row) * 64 + (((unit) ^ (((row) >> 1) & 3)) << 4)))

template <int EPI>
__device__ __forceinline__ void tg_load(uint32_t sbase, int bm, int bn,
                                        int k0, int tid)
{
    const __half* A  = (EPI == 0) ? g_x : g_ao;
    const __half* Wh = (EPI == 0) ? g_wih : g_woh;
    const __half* Wl = (EPI == 0) ? g_wil : g_wol;
#pragma unroll
    for (int u = 0; u < 2; u++) {
        int idx = u * 256 + tid;          // 0..511
        int row = idx >> 2, un = idx & 3;
        uint32_t soff = SWOFF(row, un);
        size_t ga = (size_t)(bm + row) * 1024 + k0 + un * 8;
        size_t gw = (size_t)(bn + row) * 1024 + k0 + un * 8;
        CP_ASYNC16(sbase + 0 * MATG + soff, A + ga);
        CP_ASYNC16(sbase + 1 * MATG + soff, Wh + gw);
        CP_ASYNC16(sbase + 2 * MATG + soff, Wl + gw);
    }
}

template <int EPI>
__global__ __launch_bounds__(256, 2) void gemm_mma(const float* __restrict__ bias,
                                                   float* __restrict__ out)
{
    extern __shared__ __align__(16) char smem[];
    const uint32_t sm0 = (uint32_t)__cvta_generic_to_shared(smem);

    const int tid  = threadIdx.x;
    const int lane = tid & 31;
    const int wid  = tid >> 5;
    const int wm = (wid & 3) * 32;
    const int wn = (wid >> 2) * 64;
    const int bm = blockIdx.y * 128;
    const int bn = blockIdx.x * 128;

    const int lr = lane & 7, lq = lane >> 3;
    const int arow = wm + (lq & 1) * 8 + lr;
    const int sxA  = ((arow >> 1) & 3);
    const int aub  = (lq >> 1);
    const int brow = wn + (lane & 7) + ((lane >> 4) & 1) * 8;
    const int sxB  = ((brow >> 1) & 3);
    const int bub  = ((lane >> 3) & 1);

    float c[2][8][4];
#pragma unroll
    for (int im = 0; im < 2; im++)
#pragma unroll
        for (int jn = 0; jn < 8; jn++)
#pragma unroll
            for (int q = 0; q < 4; q++) c[im][jn][q] = 0.0f;

    tg_load<EPI>(sm0 + 0 * GSTG, bm, bn, 0, tid);
    CP_COMMIT();
    tg_load<EPI>(sm0 + 1 * GSTG, bm, bn, 32, tid);
    CP_COMMIT();
    tg_load<EPI>(sm0 + 2 * GSTG, bm, bn, 64, tid);
    CP_COMMIT();

    for (int ch = 0; ch < 32; ch++) {
        if (ch <= 29)      CP_WAIT2();     // groups {ch..ch+2} pending -> ch done
        else if (ch == 30) CP_WAIT1();
        else               CP_WAIT0();
        __syncthreads();               // stage ch&3 ready; stage (ch+3)&3 free

        if (ch <= 28) {                // prefetch ch+3 into stage (ch+3)&3
            tg_load<EPI>(sm0 + ((ch + 3) & 3) * GSTG, bm, bn, (ch + 3) * 32, tid);
            CP_COMMIT();
        }

        const uint32_t st = sm0 + (ch & 3) * GSTG;
        const uint32_t tA  = st;
        const uint32_t tBh = st + 1 * MATG, tBl = st + 2 * MATG;

#pragma unroll
        for (int ks = 0; ks < 2; ks++) {
            const uint32_t aup = (uint32_t)((((ks << 1) | aub) ^ sxA) << 4);
            const uint32_t bup = (uint32_t)((((ks << 1) | bub) ^ sxB) << 4);
            uint32_t aH[2][4];
#pragma unroll
            for (int im = 0; im < 2; im++) {
                uint32_t off = (uint32_t)((arow + im * 16) * 64) + aup;
                LDSM4(aH[im][0], aH[im][1], aH[im][2], aH[im][3], tA + off);
            }
#pragma unroll
            for (int jp = 0; jp < 2; jp++) {
                uint32_t bh[2][4], bl[2][4];
#pragma unroll
                for (int j = 0; j < 2; j++) {
                    int jn2 = jp * 2 + j;
                    uint32_t off = (uint32_t)((brow + jn2 * 16) * 64) + bup;
                    LDSM4(bh[j][0], bh[j][1], bh[j][2], bh[j][3], tBh + off);
                    LDSM4(bl[j][0], bl[j][1], bl[j][2], bl[j][3], tBl + off);
                }
                // 16 MMAs over 8 independent accumulators (dep distance 8)
#pragma unroll
                for (int j = 0; j < 2; j++)
#pragma unroll
                    for (int im = 0; im < 2; im++) {
                        MMA16816(c[im][2 * (jp * 2 + j)],     aH[im], &bh[j][0]);
                        MMA16816(c[im][2 * (jp * 2 + j) + 1], aH[im], &bh[j][2]);
                    }
#pragma unroll
                for (int j = 0; j < 2; j++)
#pragma unroll
                    for (int im = 0; im < 2; im++) {
                        MMA16816(c[im][2 * (jp * 2 + j)],     aH[im], &bl[j][0]);
                        MMA16816(c[im][2 * (jp * 2 + j) + 1], aH[im], &bl[j][2]);
                    }
            }
        }
    }

    // epilogue
#pragma unroll
    for (int im = 0; im < 2; im++) {
#pragma unroll
        for (int jn = 0; jn < 8; jn++) {
            int r0 = bm + wm + im * 16 + (lane >> 2);
            int cg = bn + wn + jn * 8 + 2 * (lane & 3);
            float b0 = bias[cg], b1 = bias[cg + 1];
#pragma unroll
            for (int half = 0; half < 2; half++) {
                int r = r0 + half * 8;
                float v0 = c[im][jn][half * 2 + 0] + b0;
                float v1 = c[im][jn][half * 2 + 1] + b1;
                if (EPI == 0) {
                    int b = r >> 10, nn = r & 1023;
                    int s = cg >> 10;
                    int h = (cg >> 6) & 15;
                    int d = cg & 63;
                    size_t idx = (((size_t)b * Hh + h) * Nn + nn) * Dd + d;
                    if (s == 0) {           // Q: single fp16, QK scale folded
                        *(uint32_t*)&g_q[idx] = packh(v0 * 0.125f, v1 * 0.125f);
                    } else {                // K/V: hi/lo
                        __half* hiA = (s == 1) ? g_kh : g_vh;
                        __half* loA = (s == 1) ? g_kl : g_vl;
                        uint32_t hp, lp;
                        split2h(v0, v1, hp, lp);
                        *(uint32_t*)&hiA[idx] = hp;
                        *(uint32_t*)&loA[idx] = lp;
                    }
                } else {
                    *(float2*)&out[(size_t)r * 1024 + cg] = make_float2(v0, v1);
                }
            }
        }
    }
}

// ---------------------------------------------------------------------------
// fp16x2 MMA flash attention, 64-key tiles, 2 CTAs/SM, 3-STAGE KV ring
// (prefetch distance 2, ONE __syncthreads per tile).
// S = Q*(Kh+Kl); O += P*(Vh+Vl); P packed single fp16.
// Smem: 3 KV stages (Kh,Kl,Vh,Vl @ 64x144 = 36864 each) = 110592 B total;
// Q (single, 18432 B) staged through the stage-1 region before the loop.
// ---------------------------------------------------------------------------
#define ASTG 36864
#define AMAT 9216
#define ASMEM (3 * ASTG)              // 110592 B

__global__ __launch_bounds__(256, 2) void attn_mma()
{
    extern __shared__ __align__(16) char smem[];
    const uint32_t sm0 = (uint32_t)__cvta_generic_to_shared(smem);

    const int tid  = threadIdx.x;
    const int lane = tid & 31;
    const int wq   = tid >> 5;
    const int bh = blockIdx.y;
    const int q0 = blockIdx.x * 128;

    const __half* Qp  = g_q  + (size_t)bh * NDh;
    const __half* Khp = g_kh + (size_t)bh * NDh;
    const __half* Klp = g_kl + (size_t)bh * NDh;
    const __half* Vhp = g_vh + (size_t)bh * NDh;
    const __half* Vlp = g_vl + (size_t)bh * NDh;

    // ---- stage Q through the stage-1 region; prefetch KV tile 0 -----------
    const uint32_t qbase = sm0 + ASTG;
#pragma unroll
    for (int u = 0; u < 4; u++) {          // Q single: 128 rows x 144B
        int r = u * 32 + (tid >> 3);
        int cc = tid & 7;
        CP_ASYNC16(qbase + r * 144 + cc * 16,
                   Qp + (size_t)(q0 + r) * 64 + cc * 8);
    }
    CP_COMMIT();
    {
#pragma unroll
        for (int u = 0; u < 8; u++) {      // KV tile 0 -> stage 0
            const __half* mp = (u < 2) ? Khp : (u < 4) ? Klp
                               : (u < 6) ? Vhp : Vlp;
            int r = (u & 1) * 32 + (tid >> 3);
            int cc = tid & 7;
            CP_ASYNC16(sm0 + (u >> 1) * AMAT + r * 144 + cc * 16,
                       mp + (size_t)r * 64 + cc * 8);
        }
        CP_COMMIT();
    }
    CP_WAIT1();            // Q staged (KV0 may still be in flight)
    __syncthreads();

    uint32_t qf[4][4];
    {
        const int lr = lane & 7, lq = lane >> 3;
        uint32_t qa = qbase + (uint32_t)((wq * 16 + (lq & 1) * 8 + lr) * 144
                                         + (lq >> 1) * 16);
#pragma unroll
        for (int ks = 0; ks < 4; ks++)
            LDSM4(qf[ks][0], qf[ks][1], qf[ks][2], qf[ks][3], qa + ks * 32);
    }
    __syncthreads();       // Q smem region free; stage 1/2 may now be filled

    // prefetch KV tile 1 -> stage 1 (overlays the Q staging region)
    {
#pragma unroll
        for (int u = 0; u < 8; u++) {
            const __half* mp = (u < 2) ? Khp : (u < 4) ? Klp
                               : (u < 6) ? Vhp : Vlp;
            int r = (u & 1) * 32 + (tid >> 3);
            int cc = tid & 7;
            CP_ASYNC16(sm0 + ASTG + (u >> 1) * AMAT + r * 144 + cc * 16,
                       mp + (size_t)(64 + r) * 64 + cc * 8);
        }
        CP_COMMIT();
    }

    float o[8][4];
    float mrow[2] = {-1e30f, -1e30f}, lrow[2] = {0.0f, 0.0f};
#pragma unroll
    for (int j = 0; j < 8; j++)
#pragma unroll
        for (int q = 0; q < 4; q++) o[j][q] = 0.0f;

    for (int t = 0; t < 16; t++) {
        if (t <= 14) CP_WAIT1();       // groups {t, t+1} pending -> t done
        else         CP_WAIT0();
        __syncthreads();               // tile t ready; stage (t+2)%3 free

        if (t <= 13) {                 // prefetch tile t+2 into stage (t+2)%3
            uint32_t nb = sm0 + ((t + 2) % 3) * ASTG;
            int key0 = (t + 2) * 64;
#pragma unroll
            for (int u = 0; u < 8; u++) {
                const __half* mp = (u < 2) ? Khp : (u < 4) ? Klp
                                   : (u < 6) ? Vhp : Vlp;
                int r = (u & 1) * 32 + (tid >> 3);
                int cc = tid & 7;
                CP_ASYNC16(nb + (u >> 1) * AMAT + r * 144 + cc * 16,
                           mp + (size_t)(key0 + r) * 64 + cc * 8);
            }
            CP_COMMIT();
        }

        const uint32_t st = sm0 + (t % 3) * ASTG;

        // ---- S = Q K^T (2 MMAs per 16x16 tile) ---------------------------
        float s[8][4];
#pragma unroll
        for (int j = 0; j < 8; j++)
#pragma unroll
            for (int q = 0; q < 4; q++) s[j][q] = 0.0f;

        const uint32_t kaddr = st + (uint32_t)(((lane & 7) + ((lane >> 4) & 1) * 8) * 144
                                               + ((lane >> 3) & 1) * 16);
#pragma unroll
        for (int ks = 0; ks < 4; ks++) {
            uint32_t kh[4][4], kl[4][4];
#pragma unroll
            for (int jn2 = 0; jn2 < 4; jn2++) {
                uint32_t off = kaddr + (uint32_t)(jn2 * 16 * 144 + ks * 32);
                LDSM4(kh[jn2][0], kh[jn2][1], kh[jn2][2], kh[jn2][3], off);
                LDSM4(kl[jn2][0], kl[jn2][1], kl[jn2][2], kl[jn2][3], off + AMAT);
            }
#pragma unroll
            for (int jn2 = 0; jn2 < 4; jn2++) {
                MMA16816(s[2 * jn2],     qf[ks], &kh[jn2][0]);
                MMA16816(s[2 * jn2],     qf[ks], &kl[jn2][0]);
                MMA16816(s[2 * jn2 + 1], qf[ks], &kh[jn2][2]);
                MMA16816(s[2 * jn2 + 1], qf[ks], &kl[jn2][2]);
            }
        }

        // ---- online softmax ----------------------------------------------
#pragma unroll
        for (int r = 0; r < 2; r++) {
            float mx = -1e30f;
#pragma unroll
            for (int j = 0; j < 8; j++)
                mx = fmaxf(mx, fmaxf(s[j][2 * r], s[j][2 * r + 1]));
            mx = fmaxf(mx, __shfl_xor_sync(0xffffffffu, mx, 1));
            mx = fmaxf(mx, __shfl_xor_sync(0xffffffffu, mx, 2));
            float mnew = fmaxf(mrow[r], mx);
            float corr = __expf(mrow[r] - mnew);
            float sum = 0.0f;
#pragma unroll
            for (int j = 0; j < 8; j++) {
                s[j][2 * r]     = __expf(s[j][2 * r]     - mnew);
                s[j][2 * r + 1] = __expf(s[j][2 * r + 1] - mnew);
                sum += s[j][2 * r] + s[j][2 * r + 1];
            }
            sum += __shfl_xor_sync(0xffffffffu, sum, 1);
            sum += __shfl_xor_sync(0xffffffffu, sum, 2);
            lrow[r] = lrow[r] * corr + sum;
            mrow[r] = mnew;
#pragma unroll
            for (int j = 0; j < 8; j++) {
                o[j][2 * r]     *= corr;
                o[j][2 * r + 1] *= corr;
            }
        }

        // ---- O += P V (P single fp16) ------------------------------------
        const uint32_t vaddr = st + 2 * AMAT
            + (uint32_t)((lane & 15) * 144 + (lane >> 4) * 16);
#pragma unroll
        for (int ks2 = 0; ks2 < 4; ks2++) {
            uint32_t pa[4];
            float* s0 = s[2 * ks2];
            float* s1 = s[2 * ks2 + 1];
            pa[0] = packh(s0[0], s0[1]);
            pa[1] = packh(s0[2], s0[3]);
            pa[2] = packh(s1[0], s1[1]);
            pa[3] = packh(s1[2], s1[3]);

            uint32_t vrow = vaddr + (uint32_t)(ks2 * 16 * 144);
#pragma unroll
            for (int jd2 = 0; jd2 < 4; jd2++) {
                uint32_t vh[4], vl[4];
                uint32_t off = vrow + (uint32_t)(jd2 * 32);
                LDSM4T(vh[0], vh[1], vh[2], vh[3], off);
                LDSM4T(vl[0], vl[1], vl[2], vl[3], off + AMAT);
                MMA16816(o[2 * jd2],     pa, &vh[0]);
                MMA16816(o[2 * jd2],     pa, &vl[0]);
                MMA16816(o[2 * jd2 + 1], pa, &vh[2]);
                MMA16816(o[2 * jd2 + 1], pa, &vl[2]);
            }
        }
        // no end-of-body sync: reuse distance 3 + top sync protect WAR
    }

    // ---- normalize + write single-fp16 attention output [B,N,C] -----------
    const int b = bh >> 4, h = bh & 15;
    const int G = lane >> 2, T = lane & 3;
#pragma unroll
    for (int r = 0; r < 2; r++) {
        float inv = 1.0f / lrow[r];
        int row = q0 + wq * 16 + G + r * 8;
        size_t base = ((size_t)b * Nn + row) * Cc + h * 64;
#pragma unroll
        for (int jd = 0; jd < 8; jd++) {
            float v0 = o[jd][2 * r] * inv;
            float v1 = o[jd][2 * r + 1] * inv;
            int col = jd * 8 + 2 * T;
            *(uint32_t*)&g_ao[base + col] = packh(v0, v1);
        }
    }
}

// ---------------------------------------------------------------------------
extern "C" void kernel_launch(void* const* d_in, const int* in_sizes, int n_in,
                              void* d_out, int out_size)
{
    const float* x     = (const float*)d_in[0];
    const float* w_in  = (const float*)d_in[1];
    const float* b_in  = (const float*)d_in[2];
    const float* w_out = (const float*)d_in[3];
    const float* b_out = (const float*)d_in[4];
    float* out = (float*)d_out;

    cudaFuncSetAttribute(gemm_mma<0>,
                         cudaFuncAttributeMaxDynamicSharedMemorySize, GSMEM);
    cudaFuncSetAttribute(gemm_mma<1>,
                         cudaFuncAttributeMaxDynamicSharedMemorySize, GSMEM);
    cudaFuncSetAttribute(attn_mma,
                         cudaFuncAttributeMaxDynamicSharedMemorySize, ASMEM);

    // merged fp32 -> fp16 conversions (x single; w_in / w_out hi+lo)
    cvt_all<<<(N4X + N4WI + N4WO + 255) / 256, 256>>>(
        (const float4*)x, (const float4*)w_in, (const float4*)w_out);

    // QKV projection: 8192 x 3072 x 1024 -> q (single, scaled), k/v (hi/lo)
    gemm_mma<0><<<dim3(24, 64), 256, GSMEM>>>(b_in, nullptr);
    // Attention: 8 q-tiles x 128 (b,h), 2 CTAs/SM, 3-stage KV ring
    attn_mma<<<dim3(8, 128), 256, ASMEM>>>();
    // Output projection: 8192 x 1024 x 1024
    gemm_mma<1><<<dim3(8, 64), 256, GSMEM>>>(b_out, out);
}

// round 17
// speedup vs baseline: 1.7371x; 1.0760x over previous
#include <cuda_runtime.h>
#include <cuda_fp16.h>
#include <cstdint>

#define Bb 8
#define Nn 1024
#define Cc 1024
#define Hh 16
#define Dd 64
#define NDh (Nn * Dd)

// ---------------- scratch (device globals; allocation-free) ----------------
__device__ __align__(16) __half g_x[Bb * Nn * Cc];                // x, fp16
__device__ __align__(16) __half g_wih[3 * Cc * Cc], g_wil[3 * Cc * Cc];
__device__ __align__(16) __half g_woh[Cc * Cc], g_wol[Cc * Cc];
__device__ __align__(16) __half g_q[Bb * Hh * NDh];               // q single (scaled)
__device__ __align__(16) __half g_kh[Bb * Hh * NDh], g_kl[Bb * Hh * NDh];
__device__ __align__(16) __half g_v[Bb * Hh * NDh];               // v single
__device__ __align__(16) __half g_ao[Bb * Nn * Cc];               // attn out single

// ---------------------------- PTX helpers ----------------------------------
#define LDSM4(r0, r1, r2, r3, addr)                                          \
    asm volatile("ldmatrix.sync.aligned.m8n8.x4.shared.b16 {%0,%1,%2,%3},[%4];" \
                 : "=r"(r0), "=r"(r1), "=r"(r2), "=r"(r3) : "r"(addr))
#define LDSM4T(r0, r1, r2, r3, addr)                                         \
    asm volatile("ldmatrix.sync.aligned.m8n8.x4.trans.shared.b16 {%0,%1,%2,%3},[%4];" \
                 : "=r"(r0), "=r"(r1), "=r"(r2), "=r"(r3) : "r"(addr))
#define MMA16816(c, a, b)                                                    \
    asm volatile("mma.sync.aligned.m16n8k16.row.col.f32.f16.f16.f32 "        \
                 "{%0,%1,%2,%3},{%4,%5,%6,%7},{%8,%9},{%0,%1,%2,%3};"        \
                 : "+f"((c)[0]), "+f"((c)[1]), "+f"((c)[2]), "+f"((c)[3])    \
                 : "r"((a)[0]), "r"((a)[1]), "r"((a)[2]), "r"((a)[3]),       \
                   "r"((b)[0]), "r"((b)[1]))
#define CP_ASYNC16(dst, src)                                                 \
    asm volatile("cp.async.cg.shared.global [%0],[%1],16;" :: "r"(dst), "l"(src))
#define CP_COMMIT() asm volatile("cp.async.commit_group;")
#define CP_WAIT2()  asm volatile("cp.async.wait_group 2;")
#define CP_WAIT1()  asm volatile("cp.async.wait_group 1;")
#define CP_WAIT0()  asm volatile("cp.async.wait_group 0;")

// pack two fp32 -> f16x2 register (v1 in upper half, v0 in lower)
__device__ __forceinline__ uint32_t packh(float v0, float v1) {
    uint32_t r;
    asm("cvt.rn.f16x2.f32 %0,%1,%2;" : "=r"(r) : "f"(v1), "f"(v0));
    return r;
}
// hi/lo split of a pair: hi = fp16(v), lo = fp16(v - hi)
__device__ __forceinline__ void split2h(float v0, float v1,
                                        uint32_t& hi, uint32_t& lo) {
    __half h0 = __float2half_rn(v0), h1 = __float2half_rn(v1);
    hi = ((uint32_t)__half_as_ushort(h1) << 16) | __half_as_ushort(h0);
    lo = packh(v0 - __half2float(h0), v1 - __half2float(h1));
}

// --------------- fp32 -> fp16 conversions (single merged launch) -----------
#define N4X  (Bb * Nn * Cc / 4)
#define N4WI (3 * Cc * Cc / 4)
#define N4WO (Cc * Cc / 4)

__global__ __launch_bounds__(256) void cvt_all(const float4* __restrict__ x,
                                               const float4* __restrict__ wi,
                                               const float4* __restrict__ wo)
{
    int i = blockIdx.x * 256 + threadIdx.x;
    if (i < N4X) {                          // x -> single fp16
        float4 f = x[i];
        ((uint2*)g_x)[i] = make_uint2(packh(f.x, f.y), packh(f.z, f.w));
        return;
    }
    const float4* src;
    __half *hi, *lo;
    int j;
    if (i < N4X + N4WI)      { src = wi; hi = g_wih; lo = g_wil; j = i - N4X; }
    else if (i < N4X + N4WI + N4WO)
                             { src = wo; hi = g_woh; lo = g_wol; j = i - N4X - N4WI; }
    else return;
    float4 f = src[j];
    uint32_t h01, l01, h23, l23;
    split2h(f.x, f.y, h01, l01);
    split2h(f.z, f.w, h23, l23);
    ((uint2*)hi)[j] = make_uint2(h01, h23);
    ((uint2*)lo)[j] = make_uint2(l01, l23);
}

// ---------------------------------------------------------------------------
// fp16x2 TN GEMM (HMMA): C = A*W^T + bias ~= Ah*(Wh + Wl)
// CTA tile 128x128, BK=32, 4-stage cp.async ring, one sync/chunk, SW64.
// Warp grid 2m x 4n (warp tile 64x32): the x4-duplicated operand is the
// SINGLE-precision A (8KB) instead of hi/lo B (16KB) -> smem reads/chunk
// drop 160KB->128KB per SM (crossbar-bound fix).
// ---------------------------------------------------------------------------
#define MATG 8192
#define GSTG (3 * MATG)              // 24576 B / stage
#define GSMEM (4 * GSTG)             // 98304 B

#define SWOFF(row, unit) ((uint32_t)((row) * 64 + (((unit) ^ (((row) >> 1) & 3)) << 4)))

template <int EPI>
__device__ __forceinline__ void tg_load(uint32_t sbase, int bm, int bn,
                                        int k0, int tid)
{
    const __half* A  = (EPI == 0) ? g_x : g_ao;
    const __half* Wh = (EPI == 0) ? g_wih : g_woh;
    const __half* Wl = (EPI == 0) ? g_wil : g_wol;
#pragma unroll
    for (int u = 0; u < 2; u++) {
        int idx = u * 256 + tid;          // 0..511
        int row = idx >> 2, un = idx & 3;
        uint32_t soff = SWOFF(row, un);
        size_t ga = (size_t)(bm + row) * 1024 + k0 + un * 8;
        size_t gw = (size_t)(bn + row) * 1024 + k0 + un * 8;
        CP_ASYNC16(sbase + 0 * MATG + soff, A + ga);
        CP_ASYNC16(sbase + 1 * MATG + soff, Wh + gw);
        CP_ASYNC16(sbase + 2 * MATG + soff, Wl + gw);
    }
}

template <int EPI>
__global__ __launch_bounds__(256, 2) void gemm_mma(const float* __restrict__ bias,
                                                   float* __restrict__ out)
{
    extern __shared__ __align__(16) char smem[];
    const uint32_t sm0 = (uint32_t)__cvta_generic_to_shared(smem);

    const int tid  = threadIdx.x;
    const int lane = tid & 31;
    const int wid  = tid >> 5;
    const int wm = (wid & 1) * 64;     // 2 m-groups of 64
    const int wn = (wid >> 1) * 32;    // 4 n-groups of 32
    const int bm = blockIdx.y * 128;
    const int bn = blockIdx.x * 128;

    const int lr = lane & 7, lq = lane >> 3;
    const int arow = wm + (lq & 1) * 8 + lr;            // + im*16 (sx invariant)
    const int sxA  = ((arow >> 1) & 3);
    const int aub  = (lq >> 1);
    const int brow = wn + (lane & 7) + ((lane >> 4) & 1) * 8;  // + jn2*16
    const int sxB  = ((brow >> 1) & 3);
    const int bub  = ((lane >> 3) & 1);

    float c[4][4][4];                  // [m16 tile][n8 tile][frag]
#pragma unroll
    for (int im = 0; im < 4; im++)
#pragma unroll
        for (int jn = 0; jn < 4; jn++)
#pragma unroll
            for (int q = 0; q < 4; q++) c[im][jn][q] = 0.0f;

    tg_load<EPI>(sm0 + 0 * GSTG, bm, bn, 0, tid);
    CP_COMMIT();
    tg_load<EPI>(sm0 + 1 * GSTG, bm, bn, 32, tid);
    CP_COMMIT();
    tg_load<EPI>(sm0 + 2 * GSTG, bm, bn, 64, tid);
    CP_COMMIT();

    for (int ch = 0; ch < 32; ch++) {
        if (ch <= 29)      CP_WAIT2();
        else if (ch == 30) CP_WAIT1();
        else               CP_WAIT0();
        __syncthreads();               // stage ch&3 ready; stage (ch+3)&3 free

        if (ch <= 28) {
            tg_load<EPI>(sm0 + ((ch + 3) & 3) * GSTG, bm, bn, (ch + 3) * 32, tid);
            CP_COMMIT();
        }

        const uint32_t st = sm0 + (ch & 3) * GSTG;
        const uint32_t tA  = st;
        const uint32_t tBh = st + 1 * MATG, tBl = st + 2 * MATG;

#pragma unroll
        for (int ks = 0; ks < 2; ks++) {
            const uint32_t aup = (uint32_t)((((ks << 1) | aub) ^ sxA) << 4);
            const uint32_t bup = (uint32_t)((((ks << 1) | bub) ^ sxB) << 4);
            uint32_t aH[4][4];
#pragma unroll
            for (int im = 0; im < 4; im++) {
                uint32_t off = (uint32_t)((arow + im * 16) * 64) + aup;
                LDSM4(aH[im][0], aH[im][1], aH[im][2], aH[im][3], tA + off);
            }
#pragma unroll
            for (int jn2 = 0; jn2 < 2; jn2++) {
                uint32_t bh[4], bl[4];
                uint32_t off = (uint32_t)((brow + jn2 * 16) * 64) + bup;
                LDSM4(bh[0], bh[1], bh[2], bh[3], tBh + off);
                LDSM4(bl[0], bl[1], bl[2], bl[3], tBl + off);
                // 16 MMAs over 8 independent accumulators (dep distance 8)
#pragma unroll
                for (int im = 0; im < 4; im++) {
                    MMA16816(c[im][2 * jn2],     aH[im], &bh[0]);
                    MMA16816(c[im][2 * jn2 + 1], aH[im], &bh[2]);
                }
#pragma unroll
                for (int im = 0; im < 4; im++) {
                    MMA16816(c[im][2 * jn2],     aH[im], &bl[0]);
                    MMA16816(c[im][2 * jn2 + 1], aH[im], &bl[2]);
                }
            }
        }
    }

    // epilogue
#pragma unroll
    for (int im = 0; im < 4; im++) {
#pragma unroll
        for (int jn = 0; jn < 4; jn++) {
            int r0 = bm + wm + im * 16 + (lane >> 2);
            int cg = bn + wn + jn * 8 + 2 * (lane & 3);
            float b0 = bias[cg], b1 = bias[cg + 1];
#pragma unroll
            for (int half = 0; half < 2; half++) {
                int r = r0 + half * 8;
                float v0 = c[im][jn][half * 2 + 0] + b0;
                float v1 = c[im][jn][half * 2 + 1] + b1;
                if (EPI == 0) {
                    int b = r >> 10, nn = r & 1023;
                    int s = cg >> 10;
                    int h = (cg >> 6) & 15;
                    int d = cg & 63;
                    size_t idx = (((size_t)b * Hh + h) * Nn + nn) * Dd + d;
                    if (s == 0) {           // Q: single fp16, QK scale folded
                        *(uint32_t*)&g_q[idx] = packh(v0 * 0.125f, v1 * 0.125f);
                    } else if (s == 2) {    // V: single fp16
                        *(uint32_t*)&g_v[idx] = packh(v0, v1);
                    } else {                // K: hi/lo (exponent-sensitive)
                        uint32_t hp, lp;
                        split2h(v0, v1, hp, lp);
                        *(uint32_t*)&g_kh[idx] = hp;
                        *(uint32_t*)&g_kl[idx] = lp;
                    }
                } else {
                    *(float2*)&out[(size_t)r * 1024 + cg] = make_float2(v0, v1);
                }
            }
        }
    }
}

// ---------------------------------------------------------------------------
// fp16x2 MMA flash attention, 64-key tiles, 2 CTAs/SM, 3-stage KV ring.
// S = Q*(Kh+Kl); O += P*V (V single fp16 — O is an average, so V-rounding
// error does not amplify). Stage: Kh,Kl,V @ 64x144 = 27648 B; 3 stages.
// Q (single, 18432 B) staged through the stage-1 region before the loop.
// ---------------------------------------------------------------------------
#define AMAT 9216
#define ASTG (3 * AMAT)               // 27648 B / stage
#define ASMEM (3 * ASTG)              // 82944 B

__global__ __launch_bounds__(256, 2) void attn_mma()
{
    extern __shared__ __align__(16) char smem[];
    const uint32_t sm0 = (uint32_t)__cvta_generic_to_shared(smem);

    const int tid  = threadIdx.x;
    const int lane = tid & 31;
    const int wq   = tid >> 5;
    const int bh = blockIdx.y;
    const int q0 = blockIdx.x * 128;

    const __half* Qp  = g_q  + (size_t)bh * NDh;
    const __half* Khp = g_kh + (size_t)bh * NDh;
    const __half* Klp = g_kl + (size_t)bh * NDh;
    const __half* Vp  = g_v  + (size_t)bh * NDh;

    // ---- stage Q through the stage-1 region; prefetch KV tile 0 -----------
    const uint32_t qbase = sm0 + ASTG;
#pragma unroll
    for (int u = 0; u < 4; u++) {          // Q single: 128 rows x 144B
        int r = u * 32 + (tid >> 3);
        int cc = tid & 7;
        CP_ASYNC16(qbase + r * 144 + cc * 16,
                   Qp + (size_t)(q0 + r) * 64 + cc * 8);
    }
    CP_COMMIT();
    {
#pragma unroll
        for (int u = 0; u < 6; u++) {      // KV tile 0 -> stage 0 (Kh,Kl,V)
            const __half* mp = (u < 2) ? Khp : (u < 4) ? Klp : Vp;
            int r = (u & 1) * 32 + (tid >> 3);
            int cc = tid & 7;
            CP_ASYNC16(sm0 + (u >> 1) * AMAT + r * 144 + cc * 16,
                       mp + (size_t)r * 64 + cc * 8);
        }
        CP_COMMIT();
    }
    CP_WAIT1();            // Q staged (KV0 may still be in flight)
    __syncthreads();

    uint32_t qf[4][4];
    {
        const int lr = lane & 7, lq = lane >> 3;
        uint32_t qa = qbase + (uint32_t)((wq * 16 + (lq & 1) * 8 + lr) * 144
                                         + (lq >> 1) * 16);
#pragma unroll
        for (int ks = 0; ks < 4; ks++)
            LDSM4(qf[ks][0], qf[ks][1], qf[ks][2], qf[ks][3], qa + ks * 32);
    }
    __syncthreads();       // Q smem region free; stage 1/2 may now be filled

    // prefetch KV tile 1 -> stage 1 (overlays the Q staging region)
    {
#pragma unroll
        for (int u = 0; u < 6; u++) {
            const __half* mp = (u < 2) ? Khp : (u < 4) ? Klp : Vp;
            int r = (u & 1) * 32 + (tid >> 3);
            int cc = tid & 7;
            CP_ASYNC16(sm0 + ASTG + (u >> 1) * AMAT + r * 144 + cc * 16,
                       mp + (size_t)(64 + r) * 64 + cc * 8);
        }
        CP_COMMIT();
    }

    float o[8][4];
    float mrow[2] = {-1e30f, -1e30f}, lrow[2] = {0.0f, 0.0f};
#pragma unroll
    for (int j = 0; j < 8; j++)
#pragma unroll
        for (int q = 0; q < 4; q++) o[j][q] = 0.0f;

    for (int t = 0; t < 16; t++) {
        if (t <= 14) CP_WAIT1();       // groups {t, t+1} pending -> t done
        else         CP_WAIT0();
        __syncthreads();               // tile t ready; stage (t+2)%3 free

        if (t <= 13) {                 // prefetch tile t+2 into stage (t+2)%3
            uint32_t nb = sm0 + ((t + 2) % 3) * ASTG;
            int key0 = (t + 2) * 64;
#pragma unroll
            for (int u = 0; u < 6; u++) {
                const __half* mp = (u < 2) ? Khp : (u < 4) ? Klp : Vp;
                int r = (u & 1) * 32 + (tid >> 3);
                int cc = tid & 7;
                CP_ASYNC16(nb + (u >> 1) * AMAT + r * 144 + cc * 16,
                           mp + (size_t)(key0 + r) * 64 + cc * 8);
            }
            CP_COMMIT();
        }

        const uint32_t st = sm0 + (t % 3) * ASTG;

        // ---- S = Q K^T (2 MMAs per 16x16 tile) ---------------------------
        float s[8][4];
#pragma unroll
        for (int j = 0; j < 8; j++)
#pragma unroll
            for (int q = 0; q < 4; q++) s[j][q] = 0.0f;

        const uint32_t kaddr = st + (uint32_t)(((lane & 7) + ((lane >> 4) & 1) * 8) * 144
                                               + ((lane >> 3) & 1) * 16);
#pragma unroll
        for (int ks = 0; ks < 4; ks++) {
            uint32_t kh[4][4], kl[4][4];
#pragma unroll
            for (int jn2 = 0; jn2 < 4; jn2++) {
                uint32_t off = kaddr + (uint32_t)(jn2 * 16 * 144 + ks * 32);
                LDSM4(kh[jn2][0], kh[jn2][1], kh[jn2][2], kh[jn2][3], off);
                LDSM4(kl[jn2][0], kl[jn2][1], kl[jn2][2], kl[jn2][3], off + AMAT);
            }
#pragma unroll
            for (int jn2 = 0; jn2 < 4; jn2++) {
                MMA16816(s[2 * jn2],     qf[ks], &kh[jn2][0]);
                MMA16816(s[2 * jn2],     qf[ks], &kl[jn2][0]);
                MMA16816(s[2 * jn2 + 1], qf[ks], &kh[jn2][2]);
                MMA16816(s[2 * jn2 + 1], qf[ks], &kl[jn2][2]);
            }
        }

        // ---- online softmax ----------------------------------------------
#pragma unroll
        for (int r = 0; r < 2; r++) {
            float mx = -1e30f;
#pragma unroll
            for (int j = 0; j < 8; j++)
                mx = fmaxf(mx, fmaxf(s[j][2 * r], s[j][2 * r + 1]));
            mx = fmaxf(mx, __shfl_xor_sync(0xffffffffu, mx, 1));
            mx = fmaxf(mx, __shfl_xor_sync(0xffffffffu, mx, 2));
            float mnew = fmaxf(mrow[r], mx);
            float corr = __expf(mrow[r] - mnew);
            float sum = 0.0f;
#pragma unroll
            for (int j = 0; j < 8; j++) {
                s[j][2 * r]     = __expf(s[j][2 * r]     - mnew);
                s[j][2 * r + 1] = __expf(s[j][2 * r + 1] - mnew);
                sum += s[j][2 * r] + s[j][2 * r + 1];
            }
            sum += __shfl_xor_sync(0xffffffffu, sum, 1);
            sum += __shfl_xor_sync(0xffffffffu, sum, 2);
            lrow[r] = lrow[r] * corr + sum;
            mrow[r] = mnew;
#pragma unroll
            for (int j = 0; j < 8; j++) {
                o[j][2 * r]     *= corr;
                o[j][2 * r + 1] *= corr;
            }
        }

        // ---- O += P V (V single fp16) ------------------------------------
        const uint32_t vaddr = st + 2 * AMAT
            + (uint32_t)((lane & 15) * 144 + (lane >> 4) * 16);
#pragma unroll
        for (int ks2 = 0; ks2 < 4; ks2++) {
            uint32_t pa[4];
            float* s0 = s[2 * ks2];
            float* s1 = s[2 * ks2 + 1];
            pa[0] = packh(s0[0], s0[1]);
            pa[1] = packh(s0[2], s0[3]);
            pa[2] = packh(s1[0], s1[1]);
            pa[3] = packh(s1[2], s1[3]);

            uint32_t vrow = vaddr + (uint32_t)(ks2 * 16 * 144);
#pragma unroll
            for (int jd2 = 0; jd2 < 4; jd2++) {
                uint32_t vh[4];
                uint32_t off = vrow + (uint32_t)(jd2 * 32);
                LDSM4T(vh[0], vh[1], vh[2], vh[3], off);
                MMA16816(o[2 * jd2],     pa, &vh[0]);
                MMA16816(o[2 * jd2 + 1], pa, &vh[2]);
            }
        }
        // no end-of-body sync: reuse distance 3 + top sync protect WAR
    }

    // ---- normalize + write single-fp16 attention output [B,N,C] -----------
    const int b = bh >> 4, h = bh & 15;
    const int G = lane >> 2, T = lane & 3;
#pragma unroll
    for (int r = 0; r < 2; r++) {
        float inv = 1.0f / lrow[r];
        int row = q0 + wq * 16 + G + r * 8;
        size_t base = ((size_t)b * Nn + row) * Cc + h * 64;
#pragma unroll
        for (int jd = 0; jd < 8; jd++) {
            float v0 = o[jd][2 * r] * inv;
            float v1 = o[jd][2 * r + 1] * inv;
            int col = jd * 8 + 2 * T;
            *(uint32_t*)&g_ao[base + col] = packh(v0, v1);
        }
    }
}

// ---------------------------------------------------------------------------
extern "C" void kernel_launch(void* const* d_in, const int* in_sizes, int n_in,
                              void* d_out, int out_size)
{
    const float* x     = (const float*)d_in[0];
    const float* w_in  = (const float*)d_in[1];
    const float* b_in  = (const float*)d_in[2];
    const float* w_out = (const float*)d_in[3];
    const float* b_out = (const float*)d_in[4];
    float* out = (float*)d_out;

    cudaFuncSetAttribute(gemm_mma<0>,
                         cudaFuncAttributeMaxDynamicSharedMemorySize, GSMEM);
    cudaFuncSetAttribute(gemm_mma<1>,
                         cudaFuncAttributeMaxDynamicSharedMemorySize, GSMEM);
    cudaFuncSetAttribute(attn_mma,
                         cudaFuncAttributeMaxDynamicSharedMemorySize, ASMEM);

    // merged fp32 -> fp16 conversions (x single; w_in / w_out hi+lo)
    cvt_all<<<(N4X + N4WI + N4WO + 255) / 256, 256>>>(
        (const float4*)x, (const float4*)w_in, (const float4*)w_out);

    // QKV projection: 8192 x 3072 x 1024 -> q (single, scaled), k (hi/lo), v
    gemm_mma<0><<<dim3(24, 64), 256, GSMEM>>>(b_in, nullptr);
    // Attention: 8 q-tiles x 128 (b,h), 2 CTAs/SM, 3-stage KV ring
    attn_mma<<<dim3(8, 128), 256, ASMEM>>>();
    // Output projection: 8192 x 1024 x 1024
    gemm_mma<1><<<dim3(8, 64), 256, GSMEM>>>(b_out, out);
}